// round 15
// baseline (speedup 1.0000x reference)
#include <cuda_runtime.h>
#include <cuda_bf16.h>
#include <cuda_fp16.h>
#include <cstdint>

#define BB    2048
#define DM    128
#define FF    12800
#define NDLLM 768
#define NDFF  256
#define NE    8
#define GKP   13632        // padded gin K: 768 dkp + 1 cyc + 7 pad + 12800 xf + 56 pad
#define XOFF  776          // xf start inside padded gin (16B aligned)
#define TCG   213          // gate K chunks (GKP/64)
#define GS    4            // gate split-K
#define TSPLIT 8           // expert split-K: ~400 working CTAs -> 3 waves x 25 chunks
#define TCE   200          // expert K chunks (FF/64)
#define WSCALE 1024.0f     // weight pre-scale (power of 2: exact to undo)
#define INV_WSCALE 0.0009765625f

// ---------------- device scratch ----------------
__device__ __align__(16) __half g_gin_h[(size_t)BB * GKP];
__device__ __align__(16) __half g_gin_l[(size_t)BB * GKP];
__device__ __align__(16) __half g_w1h[(size_t)GKP * NDFF];
__device__ __align__(16) __half g_w1l[(size_t)GKP * NDFF];
__device__ __align__(16) __half g_wh[(size_t)9 * FF * DM];
__device__ __align__(16) __half g_wl[(size_t)9 * FF * DM];
__device__ float g_gate_part[(size_t)GS * BB * NDFF];
__device__ float g_exp_part[(size_t)TSPLIT * NE * BB * DM];   // 67 MB
__device__ float g_gen_part[(size_t)TSPLIT * BB * DM];
__device__ int   g_counts[NE];
__device__ int   g_list[NE * BB];
__device__ float g_gateval[NE * BB];
__device__ int   g_entry[2 * BB];

// ---------------- PTX helpers (baseline ISA only) ----------------
__device__ __forceinline__ uint32_t smem_u32(const void* p) {
    uint32_t a;
    asm("{ .reg .u64 t; cvta.to.shared.u64 t, %1; cvt.u32.u64 %0, t; }" : "=r"(a) : "l"(p));
    return a;
}
#define CP16(s, g) asm volatile("cp.async.cg.shared.global [%0], [%1], 16;" :: "r"(s), "l"(g) : "memory")
#define CP_COMMIT() asm volatile("cp.async.commit_group;" ::: "memory")
#define CP_WAIT1()  asm volatile("cp.async.wait_group 1;" ::: "memory")
#define LDSM4(R, a) asm volatile("ldmatrix.sync.aligned.m8n8.x4.shared.b16 {%0,%1,%2,%3}, [%4];" \
    : "=r"((R)[0]), "=r"((R)[1]), "=r"((R)[2]), "=r"((R)[3]) : "r"(a))
#define LDSM4T(R, a) asm volatile("ldmatrix.sync.aligned.m8n8.x4.trans.shared.b16 {%0,%1,%2,%3}, [%4];" \
    : "=r"((R)[0]), "=r"((R)[1]), "=r"((R)[2]), "=r"((R)[3]) : "r"(a))
// fp16 MMA, fp32 accumulate (sm_80 baseline ISA)
#define MMA16816H(d, a, b0, b1)                                                \
    asm volatile("mma.sync.aligned.m16n8k16.row.col.f32.f16.f16.f32 "          \
        "{%0,%1,%2,%3}, {%4,%5,%6,%7}, {%8,%9}, {%0,%1,%2,%3};"                \
        : "+f"((d)[0]), "+f"((d)[1]), "+f"((d)[2]), "+f"((d)[3])               \
        : "r"((a)[0]), "r"((a)[1]), "r"((a)[2]), "r"((a)[3]), "r"(b0), "r"(b1))

// Load all fragments of one ks-slice (16 K) into register buffer BUF.
#define LOADF(KS, BUF)                                                         \
    { const int arow = wm * 64 + (lane & 15);                                  \
      const int akb  = (KS) * 32 + ((lane >> 4) & 1) * 16;                     \
      _Pragma("unroll") for (int mi = 0; mi < 4; ++mi) {                       \
        const uint32_t off = (uint32_t)((arow + mi * 16) * 128 + akb);         \
        const uint32_t sw = off ^ ((off >> 3) & 0x70);                         \
        LDSM4(ah[BUF][mi], sA + sw); LDSM4(al[BUF][mi], sAl + sw); }           \
      const int brow = (KS) * 16 + (lane & 15);                                \
      _Pragma("unroll") for (int nj = 0; nj < 2; ++nj) {                       \
        const uint32_t off = (uint32_t)(brow * 256 + (wn * 32 + nj * 16) * 2 + ((lane >> 4) & 1) * 16); \
        const uint32_t sw = off ^ ((off >> 4) & 0x70);                         \
        LDSM4T(bh[BUF][nj], sBh + sw); LDSM4T(bl[BUF][nj], sBl + sw); } }

// Issue the 48 MMAs (3 passes) for register buffer BUF.
#define MMAS(BUF)                                                              \
    _Pragma("unroll") for (int mi = 0; mi < 4; ++mi)                           \
    _Pragma("unroll") for (int nj = 0; nj < 2; ++nj)                           \
    _Pragma("unroll") for (int hh = 0; hh < 2; ++hh) {                         \
        const int nf = nj * 2 + hh;                                            \
        MMA16816H(acc[mi][nf], ah[BUF][mi], bh[BUF][nj][hh * 2], bh[BUF][nj][hh * 2 + 1]); \
        MMA16816H(acc[mi][nf], ah[BUF][mi], bl[BUF][nj][hh * 2], bl[BUF][nj][hh * 2 + 1]); \
        MMA16816H(acc[mi][nf], al[BUF][mi], bh[BUF][nj][hh * 2], bh[BUF][nj][hh * 2 + 1]); }

// Software-pipelined chunk compute: fragments for ks+1 are loaded (LDSM)
// before the MMAs of ks issue, hiding LDSM latency under the MMA chain.
#define COMPUTE_CHUNK(SBASE)                                                   \
  { const uint32_t sA = (SBASE), sAl = sA + 16384, sBh = sA + 32768, sBl = sA + 49152; \
    uint32_t ah[2][4][4], al[2][4][4], bh[2][2][4], bl[2][2][4];               \
    LOADF(0, 0);                                                               \
    _Pragma("unroll") for (int ks = 0; ks < 4; ++ks) {                         \
      if (ks < 3) { LOADF(ks + 1, (ks + 1) & 1); }                             \
      MMAS(ks & 1);                                                            \
    } }

// ---------------------------------------------------------------------------
__global__ void init_kernel() {
    if (threadIdx.x < NE) g_counts[threadIdx.x] = 0;
}

// padded gin -> 2-term fp16 split (A operand for BOTH gate and experts)
__global__ void build_gin2_kernel(const float* __restrict__ xf, const float* __restrict__ cyc,
                                  const float* __restrict__ dkp) {
    size_t g = (size_t)blockIdx.x * blockDim.x + threadIdx.x;
    if (g >= (size_t)BB * (GKP / 2)) return;
    const int b = (int)(g / (GKP / 2));
    const int kp = (int)(g % (GKP / 2)) * 2;
    __half2 h2, l2;
#pragma unroll
    for (int u = 0; u < 2; u++) {
        const int k = kp + u;
        float x = 0.0f;
        if (k < NDLLM)                       x = dkp[(size_t)b * NDLLM + k];
        else if (k == NDLLM)                 x = cyc[b];
        else if (k >= XOFF && k < XOFF + FF) x = xf[(size_t)b * FF + (k - XOFF)];
        const __half h = __float2half_rn(x);
        const __half l = __float2half_rn(x - __half2float(h));
        if (u == 0) { h2.x = h; l2.x = l; } else { h2.y = h; l2.y = l; }
    }
    reinterpret_cast<__half2*>(g_gin_h)[g] = h2;
    reinterpret_cast<__half2*>(g_gin_l)[g] = l2;
}

// Wg1 [13569,256] -> padded row-remapped 2-term fp16 split, pre-scaled x1024
__global__ void build_w1_kernel(const float* __restrict__ Wg1) {
    size_t g = (size_t)blockIdx.x * blockDim.x + threadIdx.x;
    if (g >= (size_t)GKP * (NDFF / 2)) return;
    const int kp = (int)(g / (NDFF / 2));
    const int c2 = (int)(g % (NDFF / 2)) * 2;
    int src = -1;
    if (kp <= NDLLM) src = kp;
    else if (kp >= XOFF && kp < XOFF + FF) src = kp - 7;
    float2 v = make_float2(0.f, 0.f);
    if (src >= 0) v = *reinterpret_cast<const float2*>(&Wg1[(size_t)src * NDFF + c2]);
    v.x *= WSCALE; v.y *= WSCALE;
    __half2 h2, l2;
    h2.x = __float2half_rn(v.x);
    l2.x = __float2half_rn(v.x - __half2float(h2.x));
    h2.y = __float2half_rn(v.y);
    l2.y = __float2half_rn(v.y - __half2float(h2.y));
    reinterpret_cast<__half2*>(g_w1h)[g] = h2;
    reinterpret_cast<__half2*>(g_w1l)[g] = l2;
}

// We[8][FF][DM] ++ Wgen[FF][DM] -> 2-term fp16 split, pre-scaled x1024
__global__ void split_w_kernel(const float* __restrict__ We, const float* __restrict__ Wgen) {
    size_t g = (size_t)blockIdx.x * blockDim.x + threadIdx.x;
    const size_t half_n = (size_t)9 * FF * DM / 2;
    if (g >= half_n) return;
    const size_t we2 = (size_t)8 * FF * DM / 2;
    float2 v = (g < we2) ? reinterpret_cast<const float2*>(We)[g]
                         : reinterpret_cast<const float2*>(Wgen)[g - we2];
    v.x *= WSCALE; v.y *= WSCALE;
    __half2 h2, l2;
    h2.x = __float2half_rn(v.x);
    l2.x = __float2half_rn(v.x - __half2float(h2.x));
    h2.y = __float2half_rn(v.y);
    l2.y = __float2half_rn(v.y - __half2float(h2.y));
    reinterpret_cast<__half2*>(g_wh)[g] = h2;
    reinterpret_cast<__half2*>(g_wl)[g] = l2;
}

// ---------------------------------------------------------------------------
// gate MMA (launch slot #4): fp16 2-term, 3 passes, pipelined fragments.
// grid (16 m, 2 n, GS); CTA 128x128, BK=64, 3-stage cp.async (3 x 64KB).
// ---------------------------------------------------------------------------
__global__ void __launch_bounds__(256, 1)
gate_mma_kernel() {
    extern __shared__ __align__(1024) char dsm[];
    const int bm   = blockIdx.x * 128;
    const int nblk = blockIdx.y;
    const int s    = blockIdx.z;
    const int cb = (s * TCG) / GS;
    const int nch = ((s + 1) * TCG) / GS - cb;
    const int tid = threadIdx.x;
    const int wid = tid >> 5, lane = tid & 31;
    const int wm = wid & 1, wn = wid >> 1;

    float acc[4][4][4];
#pragma unroll
    for (int a = 0; a < 4; a++)
#pragma unroll
        for (int b = 0; b < 4; b++)
#pragma unroll
            for (int c = 0; c < 4; c++) acc[a][b][c] = 0.0f;

#define GPF(CI)                                                                \
    { const int k0 = (cb + (CI)) * 64;                                         \
      const uint32_t sb = smem_u32(dsm + ((CI) % 3) * 65536);                  \
      _Pragma("unroll") for (int i = 0; i < 4; i++) {                          \
        const int q = tid + 256 * i;                                           \
        const int m = q >> 3, kb16 = q & 7;                                    \
        const uint32_t offa = (uint32_t)(m * 128 + kb16 * 16);                 \
        const uint32_t swa = offa ^ ((offa >> 3) & 0x70);                      \
        const size_t ga = (size_t)(bm + m) * GKP + k0 + kb16 * 8;              \
        CP16(sb + swa, g_gin_h + ga);                                          \
        CP16(sb + 16384 + swa, g_gin_l + ga);                                  \
        const int kk = q >> 4, nb16 = q & 15;                                  \
        const uint32_t offb = (uint32_t)(kk * 256 + nb16 * 16);                \
        const uint32_t swb = offb ^ ((offb >> 4) & 0x70);                      \
        const size_t gb = (size_t)(k0 + kk) * NDFF + nblk * 128 + nb16 * 8;    \
        CP16(sb + 32768 + swb, g_w1h + gb);                                    \
        CP16(sb + 49152 + swb, g_w1l + gb); } }

    GPF(0);
    CP_COMMIT();
    if (nch > 1) GPF(1);
    CP_COMMIT();
    for (int c = 0; c < nch; ++c) {
        CP_WAIT1();
        __syncthreads();
        if (c + 2 < nch) GPF(c + 2);
        CP_COMMIT();
        COMPUTE_CHUNK(smem_u32(dsm + (c % 3) * 65536));
    }
#undef GPF

#pragma unroll
    for (int mi = 0; mi < 4; ++mi) {
        const int r0 = wm * 64 + mi * 16 + (lane >> 2);
        const int r1 = r0 + 8;
#pragma unroll
        for (int nf = 0; nf < 4; ++nf) {
            const int cc = wn * 32 + nf * 8 + (lane & 3) * 2;
            const size_t base = ((size_t)s * BB + bm) * NDFF + nblk * 128 + cc;
            *reinterpret_cast<float2*>(&g_gate_part[base + (size_t)r0 * NDFF]) =
                make_float2(acc[mi][nf][0], acc[mi][nf][1]);
            *reinterpret_cast<float2*>(&g_gate_part[base + (size_t)r1 * NDFF]) =
                make_float2(acc[mi][nf][2], acc[mi][nf][3]);
        }
    }
}

// ---------------------------------------------------------------------------
// gate epilogue (verbatim)
// ---------------------------------------------------------------------------
__global__ void __launch_bounds__(256)
gate_epilogue_kernel(const float* __restrict__ bg1, const float* __restrict__ Wg2,
                     const float* __restrict__ bg2) {
    const int warp = threadIdx.x >> 5;
    const int lane = threadIdx.x & 31;
    const int t = blockIdx.x * 8 + warp;
    if (t >= BB) return;

    float h[8];
#pragma unroll
    for (int j = 0; j < 8; j++) {
        const int c = lane + 32 * j;
        float v = 0.0f;
#pragma unroll
        for (int s = 0; s < GS; s++)
            v += g_gate_part[((size_t)s * BB + t) * NDFF + c];
        const float x = v * INV_WSCALE + bg1[c];
        const float inner = 0.7978845608028654f * (x + 0.044715f * x * x * x);
        h[j] = 0.5f * x * (1.0f + tanhf(inner));
    }
    float le[NE];
#pragma unroll
    for (int e = 0; e < NE; e++) {
        float s = 0.0f;
#pragma unroll
        for (int j = 0; j < 8; j++)
            s += h[j] * Wg2[(size_t)(lane + 32 * j) * NE + e];
#pragma unroll
        for (int o = 16; o > 0; o >>= 1)
            s += __shfl_xor_sync(0xffffffffu, s, o);
        le[e] = s;
    }
    if (lane == 0) {
        float logits[NE];
#pragma unroll
        for (int e = 0; e < NE; e++) logits[e] = le[e] + bg2[e];
        float mx = logits[0];
#pragma unroll
        for (int e = 1; e < NE; e++) mx = fmaxf(mx, logits[e]);
        float p[NE];
        float sum = 0.0f;
#pragma unroll
        for (int e = 0; e < NE; e++) { p[e] = expf(logits[e] - mx); sum += p[e]; }
#pragma unroll
        for (int e = 0; e < NE; e++) p[e] /= sum;
        int i1 = 0;
#pragma unroll
        for (int e = 1; e < NE; e++) if (logits[e] > logits[i1]) i1 = e;
        int i2 = (i1 == 0) ? 1 : 0;
#pragma unroll
        for (int e = 0; e < NE; e++)
            if (e != i1 && logits[e] > logits[i2]) i2 = e;
        const float denom = p[i1] + p[i2] + 1e-9f;
        int pos1 = atomicAdd(&g_counts[i1], 1);
        g_list[i1 * BB + pos1] = t;
        g_gateval[i1 * BB + pos1] = p[i1] / denom;
        g_entry[2 * t + 0] = i1 * BB + pos1;
        int pos2 = atomicAdd(&g_counts[i2], 1);
        g_list[i2 * BB + pos2] = t;
        g_gateval[i2 * BB + pos2] = p[i2] / denom;
        g_entry[2 * t + 1] = i2 * BB + pos2;
    }
}

// ---------------------------------------------------------------------------
// expert MMA: experts (slab 0..7, gathered) + general (slab 8).
// TSPLIT=8 (even 25-chunk splits): ~400 working CTAs -> 3 waves x 25 chunks.
// Pipelined fragments (same macro as gate).
// ---------------------------------------------------------------------------
__global__ void __launch_bounds__(256, 1)
mma_gemm_kernel() {
    __shared__ int s_tok[128];
    extern __shared__ __align__(1024) char dsm[];

    const int slab  = blockIdx.z;
    const int split = blockIdx.y;
    const int t0    = blockIdx.x * 128;
    const int tid   = threadIdx.x;
    const int wid   = tid >> 5, lane = tid & 31;
    const int wm    = wid & 1, wn = wid >> 1;
    const int cbk = (split * TCE) / TSPLIT;
    const int nch = ((split + 1) * TCE) / TSPLIT - cbk;   // 25 even

    int cnt = BB;
    if (slab < 8) {
        cnt = g_counts[slab];
        if (t0 >= cnt) return;
        if (tid < 128) {
            const int idx = t0 + tid;
            s_tok[tid] = (idx < cnt) ? g_list[slab * BB + idx] : 0;
        }
    } else {
        if (tid < 128) s_tok[tid] = t0 + tid;
    }
    __syncthreads();

    const __half* Wh = g_wh + (size_t)slab * FF * DM;
    const __half* Wl = g_wl + (size_t)slab * FF * DM;

#define EPF(C)                                                                 \
    {                                                                          \
        const int k0 = (cbk + (C)) * 64;                                       \
        const uint32_t sb = smem_u32(dsm + ((C) % 3) * 65536);                 \
        _Pragma("unroll")                                                      \
        for (int i = 0; i < 4; i++) {                                          \
            const int q = tid + 256 * i;                                       \
            const int m = q >> 3, kb16 = q & 7;                                \
            const uint32_t offa = (uint32_t)(m * 128 + kb16 * 16);             \
            const uint32_t swa = offa ^ ((offa >> 3) & 0x70);                  \
            const size_t ga = (size_t)s_tok[m] * GKP + XOFF + k0 + kb16 * 8;   \
            CP16(sb + swa, g_gin_h + ga);                                      \
            CP16(sb + 16384 + swa, g_gin_l + ga);                              \
            const int kk = q >> 4, nb16 = q & 15;                              \
            const uint32_t offb = (uint32_t)(kk * 256 + nb16 * 16);            \
            const uint32_t swb = offb ^ ((offb >> 4) & 0x70);                  \
            const size_t gb = (size_t)(k0 + kk) * DM + nb16 * 8;               \
            CP16(sb + 32768 + swb, Wh + gb);                                   \
            CP16(sb + 49152 + swb, Wl + gb);                                   \
        }                                                                      \
    }

    float acc[4][4][4];
#pragma unroll
    for (int a = 0; a < 4; a++)
#pragma unroll
        for (int b = 0; b < 4; b++)
#pragma unroll
            for (int c = 0; c < 4; c++) acc[a][b][c] = 0.0f;

    EPF(0);
    CP_COMMIT();
    if (nch > 1) EPF(1);
    CP_COMMIT();

    for (int c = 0; c < nch; ++c) {
        CP_WAIT1();
        __syncthreads();
        if (c + 2 < nch) EPF(c + 2);
        CP_COMMIT();
        COMPUTE_CHUNK(smem_u32(dsm + (c % 3) * 65536));
    }
#undef EPF

    float* optr;
    size_t obase;
    if (slab < 8) {
        optr = g_exp_part;
        obase = ((size_t)split * (NE * BB) + (size_t)slab * BB + t0) * DM;
    } else {
        optr = g_gen_part;
        obase = ((size_t)split * BB + t0) * DM;
    }
#pragma unroll
    for (int mi = 0; mi < 4; ++mi) {
        const int r0 = wm * 64 + mi * 16 + (lane >> 2);
        const int r1 = r0 + 8;
        const bool v0 = (t0 + r0) < cnt, v1 = (t0 + r1) < cnt;
#pragma unroll
        for (int nf = 0; nf < 4; ++nf) {
            const int cc = wn * 32 + nf * 8 + (lane & 3) * 2;
            if (v0) *reinterpret_cast<float2*>(&optr[obase + (size_t)r0 * DM + cc]) =
                make_float2(acc[mi][nf][0], acc[mi][nf][1]);
            if (v1) *reinterpret_cast<float2*>(&optr[obase + (size_t)r1 * DM + cc]) =
                make_float2(acc[mi][nf][2], acc[mi][nf][3]);
        }
    }
}

// ---------------------------------------------------------------------------
// finalize: deterministic combine over TSPLIT=8 partials, undo x1024 exactly,
// bf16 RNE cast per ref.
// ---------------------------------------------------------------------------
__global__ void finalize_kernel(const float* __restrict__ be, const float* __restrict__ bgen,
                                float* __restrict__ out) {
    const int i = blockIdx.x * blockDim.x + threadIdx.x;
    if (i >= BB * DM) return;
    const int t = i >> 7, c = i & 127;
    float comb = 0.0f;
#pragma unroll
    for (int j = 0; j < 2; ++j) {
        const int ent = g_entry[2 * t + j];
        const int e = ent >> 11;
        float dot = 0.0f;
#pragma unroll
        for (int sp = 0; sp < TSPLIT; ++sp)
            dot += g_exp_part[((size_t)sp * (NE * BB) + ent) * DM + c];
        comb += g_gateval[ent] * (dot * INV_WSCALE + be[e * DM + c]);
    }
    float gen = 0.0f;
#pragma unroll
    for (int sp = 0; sp < TSPLIT; ++sp)
        gen += g_gen_part[((size_t)sp * BB + t) * DM + c];
    gen = gen * INV_WSCALE + bgen[c];
    out[i] = gen + __bfloat162float(__float2bfloat16(comb));
}

// ---------------------------------------------------------------------------
extern "C" void kernel_launch(void* const* d_in, const int* in_sizes, int n_in,
                              void* d_out, int out_size) {
    const float* xf   = (const float*)d_in[0];
    const float* cyc  = (const float*)d_in[1];
    const float* dkp  = (const float*)d_in[2];
    const float* Wg1  = (const float*)d_in[3];
    const float* bg1  = (const float*)d_in[4];
    const float* Wg2  = (const float*)d_in[5];
    const float* bg2  = (const float*)d_in[6];
    const float* We   = (const float*)d_in[7];
    const float* be   = (const float*)d_in[8];
    const float* Wgen = (const float*)d_in[9];
    const float* bgen = (const float*)d_in[10];
    float* out = (float*)d_out;

    cudaFuncSetAttribute(gate_mma_kernel,
                         cudaFuncAttributeMaxDynamicSharedMemorySize, 196608);
    cudaFuncSetAttribute(mma_gemm_kernel,
                         cudaFuncAttributeMaxDynamicSharedMemorySize, 196608);

    // launch #4 = gate_mma_kernel -> lands in the ncu capture window
    init_kernel<<<1, 32>>>();
    build_gin2_kernel<<<(int)(((size_t)BB * (GKP / 2) + 255) / 256), 256>>>(xf, cyc, dkp);
    build_w1_kernel<<<(int)(((size_t)GKP * (NDFF / 2) + 255) / 256), 256>>>(Wg1);
    gate_mma_kernel<<<dim3(16, 2, GS), 256, 196608>>>();
    split_w_kernel<<<(int)(((size_t)9 * FF * DM / 2 + 255) / 256), 256>>>(We, Wgen);
    gate_epilogue_kernel<<<BB / 8, 256>>>(bg1, Wg2, bg2);
    mma_gemm_kernel<<<dim3(16, TSPLIT, 9), 256, 196608>>>();
    finalize_kernel<<<(BB * DM + 255) / 256, 256>>>(be, bgen, out);
}

// round 16
// speedup vs baseline: 1.0480x; 1.0480x over previous
#include <cuda_runtime.h>
#include <cuda_bf16.h>
#include <cuda_fp16.h>
#include <cstdint>

#define BB    2048
#define DM    128
#define FF    12800
#define NDLLM 768
#define NDFF  256
#define NE    8
#define GKP   13632        // padded gin K: 768 dkp + 1 cyc + 7 pad + 12800 xf + 56 pad
#define XOFF  776          // xf start inside padded gin (16B aligned)
#define TCG   213          // gate K chunks (GKP/64)
#define NTILE 32           // gate tiles: 16 m-blocks x 2 n-blocks
#define GUNITS (NTILE * TCG)   // 6816 chunk-units
#define NCTA  148
#define TSPLIT 8           // expert split-K: ~400 working CTAs -> 3 waves x 25 chunks
#define TCE   200          // expert K chunks (FF/64)
#define WSCALE 1024.0f
#define INV_WSCALE 0.0009765625f

// conv kernel section boundaries (blocks of 256 threads)
#define CB1 54528          // gin split: BB*(GKP/2)/256
#define CB2 (CB1 + 6816)   // w1 split: GKP*(NDFF/2)/256
#define CB3 (CB2 + 28800)  // w split: 9*FF*DM/2/256
#define CB4 (CB3 + 512)    // zero gate acc: BB*NDFF/(256*4)
#define CBT (CB4 + 1)      // counts init

// ---------------- device scratch ----------------
__device__ __align__(16) __half g_gin_h[(size_t)BB * GKP];
__device__ __align__(16) __half g_gin_l[(size_t)BB * GKP];
__device__ __align__(16) __half g_w1h[(size_t)GKP * NDFF];
__device__ __align__(16) __half g_w1l[(size_t)GKP * NDFF];
__device__ __align__(16) __half g_wh[(size_t)9 * FF * DM];
__device__ __align__(16) __half g_wl[(size_t)9 * FF * DM];
__device__ float g_gate_acc[(size_t)BB * NDFF];               // atomic accum
__device__ float g_exp_part[(size_t)TSPLIT * NE * BB * DM];
__device__ float g_gen_part[(size_t)TSPLIT * BB * DM];
__device__ int   g_counts[NE];
__device__ int   g_list[NE * BB];
__device__ float g_gateval[NE * BB];
__device__ int   g_entry[2 * BB];

// ---------------- PTX helpers (baseline ISA only) ----------------
__device__ __forceinline__ uint32_t smem_u32(const void* p) {
    uint32_t a;
    asm("{ .reg .u64 t; cvta.to.shared.u64 t, %1; cvt.u32.u64 %0, t; }" : "=r"(a) : "l"(p));
    return a;
}
#define CP16(s, g) asm volatile("cp.async.cg.shared.global [%0], [%1], 16;" :: "r"(s), "l"(g) : "memory")
#define CP_COMMIT() asm volatile("cp.async.commit_group;" ::: "memory")
#define CP_WAIT1()  asm volatile("cp.async.wait_group 1;" ::: "memory")
#define CP_WAIT0()  asm volatile("cp.async.wait_group 0;" ::: "memory")
#define LDSM4(R, a) asm volatile("ldmatrix.sync.aligned.m8n8.x4.shared.b16 {%0,%1,%2,%3}, [%4];" \
    : "=r"((R)[0]), "=r"((R)[1]), "=r"((R)[2]), "=r"((R)[3]) : "r"(a))
#define LDSM4T(R, a) asm volatile("ldmatrix.sync.aligned.m8n8.x4.trans.shared.b16 {%0,%1,%2,%3}, [%4];" \
    : "=r"((R)[0]), "=r"((R)[1]), "=r"((R)[2]), "=r"((R)[3]) : "r"(a))
#define MMA16816H(d, a, b0, b1)                                                \
    asm volatile("mma.sync.aligned.m16n8k16.row.col.f32.f16.f16.f32 "          \
        "{%0,%1,%2,%3}, {%4,%5,%6,%7}, {%8,%9}, {%0,%1,%2,%3};"                \
        : "+f"((d)[0]), "+f"((d)[1]), "+f"((d)[2]), "+f"((d)[3])               \
        : "r"((a)[0]), "r"((a)[1]), "r"((a)[2]), "r"((a)[3]), "r"(b0), "r"(b1))

// 3-pass 2-term fp16 compute: AhBh, AhBl, AlBh on one 64KB stage
#define COMPUTE_CHUNK(SBASE)                                                   \
  { const uint32_t sA = (SBASE), sAl = sA + 16384, sBh = sA + 32768, sBl = sA + 49152; \
    _Pragma("unroll") for (int ks = 0; ks < 4; ++ks) {                         \
      uint32_t ah[4][4], al[4][4], bh[2][4], bl[2][4];                         \
      const int arow = wm * 64 + (lane & 15);                                  \
      const int akb  = ks * 32 + ((lane >> 4) & 1) * 16;                       \
      _Pragma("unroll") for (int mi = 0; mi < 4; ++mi) {                       \
        const uint32_t off = (uint32_t)((arow + mi * 16) * 128 + akb);         \
        const uint32_t sw = off ^ ((off >> 3) & 0x70);                         \
        LDSM4(ah[mi], sA + sw); LDSM4(al[mi], sAl + sw); }                     \
      const int brow = ks * 16 + (lane & 15);                                  \
      _Pragma("unroll") for (int nj = 0; nj < 2; ++nj) {                       \
        const uint32_t off = (uint32_t)(brow * 256 + (wn * 32 + nj * 16) * 2 + ((lane >> 4) & 1) * 16); \
        const uint32_t sw = off ^ ((off >> 4) & 0x70);                         \
        LDSM4T(bh[nj], sBh + sw); LDSM4T(bl[nj], sBl + sw); }                  \
      _Pragma("unroll") for (int mi = 0; mi < 4; ++mi)                         \
      _Pragma("unroll") for (int nj = 0; nj < 2; ++nj)                         \
      _Pragma("unroll") for (int hh = 0; hh < 2; ++hh) {                       \
        const int nf = nj * 2 + hh;                                            \
        MMA16816H(acc[mi][nf], ah[mi], bh[nj][hh * 2], bh[nj][hh * 2 + 1]);    \
        MMA16816H(acc[mi][nf], ah[mi], bl[nj][hh * 2], bl[nj][hh * 2 + 1]);    \
        MMA16816H(acc[mi][nf], al[mi], bh[nj][hh * 2], bh[nj][hh * 2 + 1]); } } }

// fp16 2-term split helper
__device__ __forceinline__ void split2(float x, __half& h, __half& l) {
    h = __float2half_rn(x);
    l = __float2half_rn(x - __half2float(h));
}

// ---------------------------------------------------------------------------
// fused conversion kernel: gin split | w1 split | w split | zero acc | init
// ---------------------------------------------------------------------------
__global__ void __launch_bounds__(256)
conv_kernel(const float* __restrict__ xf, const float* __restrict__ cyc,
            const float* __restrict__ dkp, const float* __restrict__ Wg1,
            const float* __restrict__ We, const float* __restrict__ Wgen) {
    const int blk = blockIdx.x;
    const int tid = threadIdx.x;
    if (blk < CB1) {
        // padded gin -> 2-term fp16 split (A operand for gate AND experts)
        const size_t g = (size_t)blk * 256 + tid;
        const int b = (int)(g / (GKP / 2));
        const int kp = (int)(g % (GKP / 2)) * 2;
        __half2 h2, l2;
#pragma unroll
        for (int u = 0; u < 2; u++) {
            const int k = kp + u;
            float x = 0.0f;
            if (k < NDLLM)                       x = dkp[(size_t)b * NDLLM + k];
            else if (k == NDLLM)                 x = cyc[b];
            else if (k >= XOFF && k < XOFF + FF) x = xf[(size_t)b * FF + (k - XOFF)];
            __half h, l; split2(x, h, l);
            if (u == 0) { h2.x = h; l2.x = l; } else { h2.y = h; l2.y = l; }
        }
        reinterpret_cast<__half2*>(g_gin_h)[g] = h2;
        reinterpret_cast<__half2*>(g_gin_l)[g] = l2;
    } else if (blk < CB2) {
        // Wg1 -> padded row-remapped split, pre-scaled x1024
        const size_t g = (size_t)(blk - CB1) * 256 + tid;
        const int kp = (int)(g / (NDFF / 2));
        const int c2 = (int)(g % (NDFF / 2)) * 2;
        int src = -1;
        if (kp <= NDLLM) src = kp;
        else if (kp >= XOFF && kp < XOFF + FF) src = kp - 7;
        float2 v = make_float2(0.f, 0.f);
        if (src >= 0) v = *reinterpret_cast<const float2*>(&Wg1[(size_t)src * NDFF + c2]);
        __half2 h2, l2;
        split2(v.x * WSCALE, h2.x, l2.x);
        split2(v.y * WSCALE, h2.y, l2.y);
        reinterpret_cast<__half2*>(g_w1h)[g] = h2;
        reinterpret_cast<__half2*>(g_w1l)[g] = l2;
    } else if (blk < CB3) {
        // We ++ Wgen -> split, pre-scaled x1024
        const size_t g = (size_t)(blk - CB2) * 256 + tid;
        const size_t we2 = (size_t)8 * FF * DM / 2;
        float2 v = (g < we2) ? reinterpret_cast<const float2*>(We)[g]
                             : reinterpret_cast<const float2*>(Wgen)[g - we2];
        __half2 h2, l2;
        split2(v.x * WSCALE, h2.x, l2.x);
        split2(v.y * WSCALE, h2.y, l2.y);
        reinterpret_cast<__half2*>(g_wh)[g] = h2;
        reinterpret_cast<__half2*>(g_wl)[g] = l2;
    } else if (blk < CB4) {
        const size_t g = (size_t)(blk - CB3) * 1024 + tid * 4;
        *reinterpret_cast<float4*>(&g_gate_acc[g]) = make_float4(0.f, 0.f, 0.f, 0.f);
    } else {
        if (tid < NE) g_counts[tid] = 0;
    }
}

// ---------------------------------------------------------------------------
// gate MMA: balanced ragged K-partition. 148 CTAs x ~46 chunk-units.
// Each CTA covers <=2 tile-segments; partials atomically accumulated.
// ---------------------------------------------------------------------------
__global__ void __launch_bounds__(256, 1)
gate_mma_kernel() {
    extern __shared__ __align__(1024) char dsm[];
    const int cid = blockIdx.x;
    int beg = (cid * GUNITS) / NCTA;
    const int end = ((cid + 1) * GUNITS) / NCTA;
    const int tid = threadIdx.x;
    const int wid = tid >> 5, lane = tid & 31;
    const int wm = wid & 1, wn = wid >> 1;

    while (beg < end) {
        const int tile = beg / TCG;
        const int cb = beg - tile * TCG;
        const int segend = min(end, (tile + 1) * TCG);
        const int nch = segend - beg;
        const int bm = (tile >> 1) * 128;
        const int nblk = tile & 1;

        float acc[4][4][4];
#pragma unroll
        for (int a = 0; a < 4; a++)
#pragma unroll
            for (int b = 0; b < 4; b++)
#pragma unroll
                for (int c = 0; c < 4; c++) acc[a][b][c] = 0.0f;

#define GPF(CI)                                                                \
    { const int k0 = (cb + (CI)) * 64;                                         \
      const uint32_t sb = smem_u32(dsm + ((CI) % 3) * 65536);                  \
      _Pragma("unroll") for (int i = 0; i < 4; i++) {                          \
        const int q = tid + 256 * i;                                           \
        const int m = q >> 3, kb16 = q & 7;                                    \
        const uint32_t offa = (uint32_t)(m * 128 + kb16 * 16);                 \
        const uint32_t swa = offa ^ ((offa >> 3) & 0x70);                      \
        const size_t ga = (size_t)(bm + m) * GKP + k0 + kb16 * 8;              \
        CP16(sb + swa, g_gin_h + ga);                                          \
        CP16(sb + 16384 + swa, g_gin_l + ga);                                  \
        const int kk = q >> 4, nb16 = q & 15;                                  \
        const uint32_t offb = (uint32_t)(kk * 256 + nb16 * 16);                \
        const uint32_t swb = offb ^ ((offb >> 4) & 0x70);                      \
        const size_t gb = (size_t)(k0 + kk) * NDFF + nblk * 128 + nb16 * 8;    \
        CP16(sb + 32768 + swb, g_w1h + gb);                                    \
        CP16(sb + 49152 + swb, g_w1l + gb); } }

        GPF(0);
        CP_COMMIT();
        if (nch > 1) GPF(1);
        CP_COMMIT();
        for (int c = 0; c < nch; ++c) {
            CP_WAIT1();
            __syncthreads();
            if (c + 2 < nch) GPF(c + 2);
            CP_COMMIT();
            COMPUTE_CHUNK(smem_u32(dsm + (c % 3) * 65536));
        }
#undef GPF

        // atomic accumulate this segment's partial into g_gate_acc
#pragma unroll
        for (int mi = 0; mi < 4; ++mi) {
            const int r0 = wm * 64 + mi * 16 + (lane >> 2);
            const int r1 = r0 + 8;
#pragma unroll
            for (int nf = 0; nf < 4; ++nf) {
                const int cc = wn * 32 + nf * 8 + (lane & 3) * 2;
                const size_t b0 = (size_t)(bm + r0) * NDFF + nblk * 128 + cc;
                const size_t b1 = (size_t)(bm + r1) * NDFF + nblk * 128 + cc;
                atomicAdd(&g_gate_acc[b0],     acc[mi][nf][0]);
                atomicAdd(&g_gate_acc[b0 + 1], acc[mi][nf][1]);
                atomicAdd(&g_gate_acc[b1],     acc[mi][nf][2]);
                atomicAdd(&g_gate_acc[b1 + 1], acc[mi][nf][3]);
            }
        }
        CP_WAIT0();
        __syncthreads();   // smem safe for next segment's prologue
        beg = segend;
    }
}

// ---------------------------------------------------------------------------
// gate epilogue: read accumulated logits-layer, gelu, @Wg2+bg2, top-2, dispatch.
// ---------------------------------------------------------------------------
__global__ void __launch_bounds__(256)
gate_epilogue_kernel(const float* __restrict__ bg1, const float* __restrict__ Wg2,
                     const float* __restrict__ bg2) {
    const int warp = threadIdx.x >> 5;
    const int lane = threadIdx.x & 31;
    const int t = blockIdx.x * 8 + warp;
    if (t >= BB) return;

    float h[8];
#pragma unroll
    for (int j = 0; j < 8; j++) {
        const int c = lane + 32 * j;
        const float v = g_gate_acc[(size_t)t * NDFF + c];
        const float x = v * INV_WSCALE + bg1[c];
        const float inner = 0.7978845608028654f * (x + 0.044715f * x * x * x);
        h[j] = 0.5f * x * (1.0f + tanhf(inner));
    }
    float le[NE];
#pragma unroll
    for (int e = 0; e < NE; e++) {
        float s = 0.0f;
#pragma unroll
        for (int j = 0; j < 8; j++)
            s += h[j] * Wg2[(size_t)(lane + 32 * j) * NE + e];
#pragma unroll
        for (int o = 16; o > 0; o >>= 1)
            s += __shfl_xor_sync(0xffffffffu, s, o);
        le[e] = s;
    }
    if (lane == 0) {
        float logits[NE];
#pragma unroll
        for (int e = 0; e < NE; e++) logits[e] = le[e] + bg2[e];
        float mx = logits[0];
#pragma unroll
        for (int e = 1; e < NE; e++) mx = fmaxf(mx, logits[e]);
        float p[NE];
        float sum = 0.0f;
#pragma unroll
        for (int e = 0; e < NE; e++) { p[e] = expf(logits[e] - mx); sum += p[e]; }
#pragma unroll
        for (int e = 0; e < NE; e++) p[e] /= sum;
        int i1 = 0;
#pragma unroll
        for (int e = 1; e < NE; e++) if (logits[e] > logits[i1]) i1 = e;
        int i2 = (i1 == 0) ? 1 : 0;
#pragma unroll
        for (int e = 0; e < NE; e++)
            if (e != i1 && logits[e] > logits[i2]) i2 = e;
        const float denom = p[i1] + p[i2] + 1e-9f;
        int pos1 = atomicAdd(&g_counts[i1], 1);
        g_list[i1 * BB + pos1] = t;
        g_gateval[i1 * BB + pos1] = p[i1] / denom;
        g_entry[2 * t + 0] = i1 * BB + pos1;
        int pos2 = atomicAdd(&g_counts[i2], 1);
        g_list[i2 * BB + pos2] = t;
        g_gateval[i2 * BB + pos2] = p[i2] / denom;
        g_entry[2 * t + 1] = i2 * BB + pos2;
    }
}

// ---------------------------------------------------------------------------
// expert MMA (launch slot #4 -> ncu window): experts (slab 0..7) + general (8).
// TSPLIT=8 (even 25-chunk splits): ~400 working CTAs -> 3 waves x 25 chunks.
// ---------------------------------------------------------------------------
__global__ void __launch_bounds__(256, 1)
mma_gemm_kernel() {
    __shared__ int s_tok[128];
    extern __shared__ __align__(1024) char dsm[];

    const int slab  = blockIdx.z;
    const int split = blockIdx.y;
    const int t0    = blockIdx.x * 128;
    const int tid   = threadIdx.x;
    const int wid   = tid >> 5, lane = tid & 31;
    const int wm    = wid & 1, wn = wid >> 1;
    const int cbk = (split * TCE) / TSPLIT;
    const int nch = ((split + 1) * TCE) / TSPLIT - cbk;   // 25 even

    int cnt = BB;
    if (slab < 8) {
        cnt = g_counts[slab];
        if (t0 >= cnt) return;
        if (tid < 128) {
            const int idx = t0 + tid;
            s_tok[tid] = (idx < cnt) ? g_list[slab * BB + idx] : 0;
        }
    } else {
        if (tid < 128) s_tok[tid] = t0 + tid;
    }
    __syncthreads();

    const __half* Wh = g_wh + (size_t)slab * FF * DM;
    const __half* Wl = g_wl + (size_t)slab * FF * DM;

#define EPF(C)                                                                 \
    {                                                                          \
        const int k0 = (cbk + (C)) * 64;                                       \
        const uint32_t sb = smem_u32(dsm + ((C) % 3) * 65536);                 \
        _Pragma("unroll")                                                      \
        for (int i = 0; i < 4; i++) {                                          \
            const int q = tid + 256 * i;                                       \
            const int m = q >> 3, kb16 = q & 7;                                \
            const uint32_t offa = (uint32_t)(m * 128 + kb16 * 16);             \
            const uint32_t swa = offa ^ ((offa >> 3) & 0x70);                  \
            const size_t ga = (size_t)s_tok[m] * GKP + XOFF + k0 + kb16 * 8;   \
            CP16(sb + swa, g_gin_h + ga);                                      \
            CP16(sb + 16384 + swa, g_gin_l + ga);                              \
            const int kk = q >> 4, nb16 = q & 15;                              \
            const uint32_t offb = (uint32_t)(kk * 256 + nb16 * 16);            \
            const uint32_t swb = offb ^ ((offb >> 4) & 0x70);                  \
            const size_t gb = (size_t)(k0 + kk) * DM + nb16 * 8;               \
            CP16(sb + 32768 + swb, Wh + gb);                                   \
            CP16(sb + 49152 + swb, Wl + gb);                                   \
        }                                                                      \
    }

    float acc[4][4][4];
#pragma unroll
    for (int a = 0; a < 4; a++)
#pragma unroll
        for (int b = 0; b < 4; b++)
#pragma unroll
            for (int c = 0; c < 4; c++) acc[a][b][c] = 0.0f;

    EPF(0);
    CP_COMMIT();
    if (nch > 1) EPF(1);
    CP_COMMIT();

    for (int c = 0; c < nch; ++c) {
        CP_WAIT1();
        __syncthreads();
        if (c + 2 < nch) EPF(c + 2);
        CP_COMMIT();
        COMPUTE_CHUNK(smem_u32(dsm + (c % 3) * 65536));
    }
#undef EPF

    float* optr;
    size_t obase;
    if (slab < 8) {
        optr = g_exp_part;
        obase = ((size_t)split * (NE * BB) + (size_t)slab * BB + t0) * DM;
    } else {
        optr = g_gen_part;
        obase = ((size_t)split * BB + t0) * DM;
    }
#pragma unroll
    for (int mi = 0; mi < 4; ++mi) {
        const int r0 = wm * 64 + mi * 16 + (lane >> 2);
        const int r1 = r0 + 8;
        const bool v0 = (t0 + r0) < cnt, v1 = (t0 + r1) < cnt;
#pragma unroll
        for (int nf = 0; nf < 4; ++nf) {
            const int cc = wn * 32 + nf * 8 + (lane & 3) * 2;
            if (v0) *reinterpret_cast<float2*>(&optr[obase + (size_t)r0 * DM + cc]) =
                make_float2(acc[mi][nf][0], acc[mi][nf][1]);
            if (v1) *reinterpret_cast<float2*>(&optr[obase + (size_t)r1 * DM + cc]) =
                make_float2(acc[mi][nf][2], acc[mi][nf][3]);
        }
    }
}

// ---------------------------------------------------------------------------
// finalize: deterministic combine over TSPLIT=8 partials, undo x1024 exactly,
// bf16 RNE cast per ref.
// ---------------------------------------------------------------------------
__global__ void finalize_kernel(const float* __restrict__ be, const float* __restrict__ bgen,
                                float* __restrict__ out) {
    const int i = blockIdx.x * blockDim.x + threadIdx.x;
    if (i >= BB * DM) return;
    const int t = i >> 7, c = i & 127;
    float comb = 0.0f;
#pragma unroll
    for (int j = 0; j < 2; ++j) {
        const int ent = g_entry[2 * t + j];
        const int e = ent >> 11;
        float dot = 0.0f;
#pragma unroll
        for (int sp = 0; sp < TSPLIT; ++sp)
            dot += g_exp_part[((size_t)sp * (NE * BB) + ent) * DM + c];
        comb += g_gateval[ent] * (dot * INV_WSCALE + be[e * DM + c]);
    }
    float gen = 0.0f;
#pragma unroll
    for (int sp = 0; sp < TSPLIT; ++sp)
        gen += g_gen_part[((size_t)sp * BB + t) * DM + c];
    gen = gen * INV_WSCALE + bgen[c];
    out[i] = gen + __bfloat162float(__float2bfloat16(comb));
}

// ---------------------------------------------------------------------------
extern "C" void kernel_launch(void* const* d_in, const int* in_sizes, int n_in,
                              void* d_out, int out_size) {
    const float* xf   = (const float*)d_in[0];
    const float* cyc  = (const float*)d_in[1];
    const float* dkp  = (const float*)d_in[2];
    const float* Wg1  = (const float*)d_in[3];
    const float* bg1  = (const float*)d_in[4];
    const float* Wg2  = (const float*)d_in[5];
    const float* bg2  = (const float*)d_in[6];
    const float* We   = (const float*)d_in[7];
    const float* be   = (const float*)d_in[8];
    const float* Wgen = (const float*)d_in[9];
    const float* bgen = (const float*)d_in[10];
    float* out = (float*)d_out;

    cudaFuncSetAttribute(gate_mma_kernel,
                         cudaFuncAttributeMaxDynamicSharedMemorySize, 196608);
    cudaFuncSetAttribute(mma_gemm_kernel,
                         cudaFuncAttributeMaxDynamicSharedMemorySize, 196608);

    // launches: conv(1), gate(2), epilogue(3), expert(4 = ncu slot), finalize(5)
    conv_kernel<<<CBT, 256>>>(xf, cyc, dkp, Wg1, We, Wgen);
    gate_mma_kernel<<<NCTA, 256, 196608>>>();
    gate_epilogue_kernel<<<BB / 8, 256>>>(bg1, Wg2, bg2);
    mma_gemm_kernel<<<dim3(16, TSPLIT, 9), 256, 196608>>>();
    finalize_kernel<<<(BB * DM + 255) / 256, 256>>>(be, bgen, out);
}

// round 17
// speedup vs baseline: 1.0862x; 1.0365x over previous
#include <cuda_runtime.h>
#include <cuda_bf16.h>
#include <cuda_fp16.h>
#include <cstdint>

#define BB    2048
#define DM    128
#define FF    12800
#define NDLLM 768
#define NDFF  256
#define NE    8
#define GKP   13632        // padded gin K: 768 dkp + 1 cyc + 7 pad + 12800 xf + 56 pad
#define XOFF  776          // xf start inside padded gin (16B aligned)
#define TCG   213          // gate K chunks (GKP/64)
#define NTILE 32           // gate tiles: 16 m-blocks x 2 n-blocks
#define GUNITS (NTILE * TCG)   // 6816 chunk-units
#define NCTA  148
#define TCE   200          // expert K chunks (FF/64)
#define WSCALE 1024.0f
#define INV_WSCALE 0.0009765625f

// conv kernel section boundaries (blocks of 256 threads)
#define CB1 54528            // gin split: BB*(GKP/2)/256
#define CB2 (CB1 + 6816)     // w1 split: GKP*(NDFF/2)/256
#define CB3 (CB2 + 28800)    // w split: 9*FF*DM/2/256
#define CB4 (CB3 + 512)      // zero gate acc: BB*NDFF/1024
#define CB5 (CB4 + 2048)     // zero exp acc: NE*BB*DM/1024
#define CB6 (CB5 + 256)      // zero gen acc: BB*DM/1024
#define CBT (CB6 + 1)        // counts init

// ---------------- device scratch ----------------
__device__ __align__(16) __half g_gin_h[(size_t)BB * GKP];
__device__ __align__(16) __half g_gin_l[(size_t)BB * GKP];
__device__ __align__(16) __half g_w1h[(size_t)GKP * NDFF];
__device__ __align__(16) __half g_w1l[(size_t)GKP * NDFF];
__device__ __align__(16) __half g_wh[(size_t)9 * FF * DM];
__device__ __align__(16) __half g_wl[(size_t)9 * FF * DM];
__device__ float g_gate_acc[(size_t)BB * NDFF];      // atomic accum
__device__ float g_exp_acc[(size_t)NE * BB * DM];    // atomic accum (dense per expert-slot)
__device__ float g_gen_acc[(size_t)BB * DM];         // atomic accum
__device__ int   g_counts[NE];
__device__ int   g_list[NE * BB];
__device__ float g_gateval[NE * BB];
__device__ int   g_entry[2 * BB];

// ---------------- PTX helpers (baseline ISA only) ----------------
__device__ __forceinline__ uint32_t smem_u32(const void* p) {
    uint32_t a;
    asm("{ .reg .u64 t; cvta.to.shared.u64 t, %1; cvt.u32.u64 %0, t; }" : "=r"(a) : "l"(p));
    return a;
}
#define CP16(s, g) asm volatile("cp.async.cg.shared.global [%0], [%1], 16;" :: "r"(s), "l"(g) : "memory")
#define CP_COMMIT() asm volatile("cp.async.commit_group;" ::: "memory")
#define CP_WAIT1()  asm volatile("cp.async.wait_group 1;" ::: "memory")
#define LDSM4(R, a) asm volatile("ldmatrix.sync.aligned.m8n8.x4.shared.b16 {%0,%1,%2,%3}, [%4];" \
    : "=r"((R)[0]), "=r"((R)[1]), "=r"((R)[2]), "=r"((R)[3]) : "r"(a))
#define LDSM4T(R, a) asm volatile("ldmatrix.sync.aligned.m8n8.x4.trans.shared.b16 {%0,%1,%2,%3}, [%4];" \
    : "=r"((R)[0]), "=r"((R)[1]), "=r"((R)[2]), "=r"((R)[3]) : "r"(a))
#define MMA16816H(d, a, b0, b1)                                                \
    asm volatile("mma.sync.aligned.m16n8k16.row.col.f32.f16.f16.f32 "          \
        "{%0,%1,%2,%3}, {%4,%5,%6,%7}, {%8,%9}, {%0,%1,%2,%3};"                \
        : "+f"((d)[0]), "+f"((d)[1]), "+f"((d)[2]), "+f"((d)[3])               \
        : "r"((a)[0]), "r"((a)[1]), "r"((a)[2]), "r"((a)[3]), "r"(b0), "r"(b1))

// 3-pass 2-term fp16 compute: AhBh, AhBl, AlBh on one 64KB stage
#define COMPUTE_CHUNK(SBASE)                                                   \
  { const uint32_t sA = (SBASE), sAl = sA + 16384, sBh = sA + 32768, sBl = sA + 49152; \
    _Pragma("unroll") for (int ks = 0; ks < 4; ++ks) {                         \
      uint32_t ah[4][4], al[4][4], bh[2][4], bl[2][4];                         \
      const int arow = wm * 64 + (lane & 15);                                  \
      const int akb  = ks * 32 + ((lane >> 4) & 1) * 16;                       \
      _Pragma("unroll") for (int mi = 0; mi < 4; ++mi) {                       \
        const uint32_t off = (uint32_t)((arow + mi * 16) * 128 + akb);         \
        const uint32_t sw = off ^ ((off >> 3) & 0x70);                         \
        LDSM4(ah[mi], sA + sw); LDSM4(al[mi], sAl + sw); }                     \
      const int brow = ks * 16 + (lane & 15);                                  \
      _Pragma("unroll") for (int nj = 0; nj < 2; ++nj) {                       \
        const uint32_t off = (uint32_t)(brow * 256 + (wn * 32 + nj * 16) * 2 + ((lane >> 4) & 1) * 16); \
        const uint32_t sw = off ^ ((off >> 4) & 0x70);                         \
        LDSM4T(bh[nj], sBh + sw); LDSM4T(bl[nj], sBl + sw); }                  \
      _Pragma("unroll") for (int mi = 0; mi < 4; ++mi)                         \
      _Pragma("unroll") for (int nj = 0; nj < 2; ++nj)                         \
      _Pragma("unroll") for (int hh = 0; hh < 2; ++hh) {                       \
        const int nf = nj * 2 + hh;                                            \
        MMA16816H(acc[mi][nf], ah[mi], bh[nj][hh * 2], bh[nj][hh * 2 + 1]);    \
        MMA16816H(acc[mi][nf], ah[mi], bl[nj][hh * 2], bl[nj][hh * 2 + 1]);    \
        MMA16816H(acc[mi][nf], al[mi], bh[nj][hh * 2], bh[nj][hh * 2 + 1]); } } }

__device__ __forceinline__ void split2(float x, __half& h, __half& l) {
    h = __float2half_rn(x);
    l = __float2half_rn(x - __half2float(h));
}

// ---------------------------------------------------------------------------
// fused conversion kernel: gin | w1 | w splits, zero accumulators, init counts
// ---------------------------------------------------------------------------
__global__ void __launch_bounds__(256)
conv_kernel(const float* __restrict__ xf, const float* __restrict__ cyc,
            const float* __restrict__ dkp, const float* __restrict__ Wg1,
            const float* __restrict__ We, const float* __restrict__ Wgen) {
    const int blk = blockIdx.x;
    const int tid = threadIdx.x;
    if (blk < CB1) {
        const size_t g = (size_t)blk * 256 + tid;
        const int b = (int)(g / (GKP / 2));
        const int kp = (int)(g % (GKP / 2)) * 2;
        __half2 h2, l2;
#pragma unroll
        for (int u = 0; u < 2; u++) {
            const int k = kp + u;
            float x = 0.0f;
            if (k < NDLLM)                       x = dkp[(size_t)b * NDLLM + k];
            else if (k == NDLLM)                 x = cyc[b];
            else if (k >= XOFF && k < XOFF + FF) x = xf[(size_t)b * FF + (k - XOFF)];
            __half h, l; split2(x, h, l);
            if (u == 0) { h2.x = h; l2.x = l; } else { h2.y = h; l2.y = l; }
        }
        reinterpret_cast<__half2*>(g_gin_h)[g] = h2;
        reinterpret_cast<__half2*>(g_gin_l)[g] = l2;
    } else if (blk < CB2) {
        const size_t g = (size_t)(blk - CB1) * 256 + tid;
        const int kp = (int)(g / (NDFF / 2));
        const int c2 = (int)(g % (NDFF / 2)) * 2;
        int src = -1;
        if (kp <= NDLLM) src = kp;
        else if (kp >= XOFF && kp < XOFF + FF) src = kp - 7;
        float2 v = make_float2(0.f, 0.f);
        if (src >= 0) v = *reinterpret_cast<const float2*>(&Wg1[(size_t)src * NDFF + c2]);
        __half2 h2, l2;
        split2(v.x * WSCALE, h2.x, l2.x);
        split2(v.y * WSCALE, h2.y, l2.y);
        reinterpret_cast<__half2*>(g_w1h)[g] = h2;
        reinterpret_cast<__half2*>(g_w1l)[g] = l2;
    } else if (blk < CB3) {
        const size_t g = (size_t)(blk - CB2) * 256 + tid;
        const size_t we2 = (size_t)8 * FF * DM / 2;
        float2 v = (g < we2) ? reinterpret_cast<const float2*>(We)[g]
                             : reinterpret_cast<const float2*>(Wgen)[g - we2];
        __half2 h2, l2;
        split2(v.x * WSCALE, h2.x, l2.x);
        split2(v.y * WSCALE, h2.y, l2.y);
        reinterpret_cast<__half2*>(g_wh)[g] = h2;
        reinterpret_cast<__half2*>(g_wl)[g] = l2;
    } else if (blk < CB4) {
        const size_t g = (size_t)(blk - CB3) * 1024 + tid * 4;
        *reinterpret_cast<float4*>(&g_gate_acc[g]) = make_float4(0.f, 0.f, 0.f, 0.f);
    } else if (blk < CB5) {
        const size_t g = (size_t)(blk - CB4) * 1024 + tid * 4;
        *reinterpret_cast<float4*>(&g_exp_acc[g]) = make_float4(0.f, 0.f, 0.f, 0.f);
    } else if (blk < CB6) {
        const size_t g = (size_t)(blk - CB5) * 1024 + tid * 4;
        *reinterpret_cast<float4*>(&g_gen_acc[g]) = make_float4(0.f, 0.f, 0.f, 0.f);
    } else {
        if (tid < NE) g_counts[tid] = 0;
    }
}

// ---------------------------------------------------------------------------
// gate MMA (R15-proven): balanced ragged K-partition, 148 CTAs, atomic accum.
// ---------------------------------------------------------------------------
__global__ void __launch_bounds__(256, 1)
gate_mma_kernel() {
    extern __shared__ __align__(1024) char dsm[];
    const int cid = blockIdx.x;
    int beg = (cid * GUNITS) / NCTA;
    const int end = ((cid + 1) * GUNITS) / NCTA;
    const int tid = threadIdx.x;
    const int wid = tid >> 5, lane = tid & 31;
    const int wm = wid & 1, wn = wid >> 1;

    while (beg < end) {
        const int tile = beg / TCG;
        const int cb = beg - tile * TCG;
        const int segend = min(end, (tile + 1) * TCG);
        const int nch = segend - beg;
        const int bm = (tile >> 1) * 128;
        const int nblk = tile & 1;

        float acc[4][4][4];
#pragma unroll
        for (int a = 0; a < 4; a++)
#pragma unroll
            for (int b = 0; b < 4; b++)
#pragma unroll
                for (int c = 0; c < 4; c++) acc[a][b][c] = 0.0f;

#define GPF(CI)                                                                \
    { const int k0 = (cb + (CI)) * 64;                                         \
      const uint32_t sb = smem_u32(dsm + ((CI) % 3) * 65536);                  \
      _Pragma("unroll") for (int i = 0; i < 4; i++) {                          \
        const int q = tid + 256 * i;                                           \
        const int m = q >> 3, kb16 = q & 7;                                    \
        const uint32_t offa = (uint32_t)(m * 128 + kb16 * 16);                 \
        const uint32_t swa = offa ^ ((offa >> 3) & 0x70);                      \
        const size_t ga = (size_t)(bm + m) * GKP + k0 + kb16 * 8;              \
        CP16(sb + swa, g_gin_h + ga);                                          \
        CP16(sb + 16384 + swa, g_gin_l + ga);                                  \
        const int kk = q >> 4, nb16 = q & 15;                                  \
        const uint32_t offb = (uint32_t)(kk * 256 + nb16 * 16);                \
        const uint32_t swb = offb ^ ((offb >> 4) & 0x70);                      \
        const size_t gb = (size_t)(k0 + kk) * NDFF + nblk * 128 + nb16 * 8;    \
        CP16(sb + 32768 + swb, g_w1h + gb);                                    \
        CP16(sb + 49152 + swb, g_w1l + gb); } }

        GPF(0);
        CP_COMMIT();
        if (nch > 1) GPF(1);
        CP_COMMIT();
        for (int c = 0; c < nch; ++c) {
            CP_WAIT1();
            __syncthreads();
            if (c + 2 < nch) GPF(c + 2);
            CP_COMMIT();
            COMPUTE_CHUNK(smem_u32(dsm + (c % 3) * 65536));
        }
#undef GPF

#pragma unroll
        for (int mi = 0; mi < 4; ++mi) {
            const int r0 = wm * 64 + mi * 16 + (lane >> 2);
            const int r1 = r0 + 8;
#pragma unroll
            for (int nf = 0; nf < 4; ++nf) {
                const int cc = wn * 32 + nf * 8 + (lane & 3) * 2;
                const size_t b0 = (size_t)(bm + r0) * NDFF + nblk * 128 + cc;
                const size_t b1 = (size_t)(bm + r1) * NDFF + nblk * 128 + cc;
                atomicAdd(&g_gate_acc[b0],     acc[mi][nf][0]);
                atomicAdd(&g_gate_acc[b0 + 1], acc[mi][nf][1]);
                atomicAdd(&g_gate_acc[b1],     acc[mi][nf][2]);
                atomicAdd(&g_gate_acc[b1 + 1], acc[mi][nf][3]);
            }
        }
        __syncthreads();   // all warps past compute before next segment reuses smem
        beg = segend;
    }
}

// ---------------------------------------------------------------------------
// gate epilogue (R15 verbatim)
// ---------------------------------------------------------------------------
__global__ void __launch_bounds__(256)
gate_epilogue_kernel(const float* __restrict__ bg1, const float* __restrict__ Wg2,
                     const float* __restrict__ bg2) {
    const int warp = threadIdx.x >> 5;
    const int lane = threadIdx.x & 31;
    const int t = blockIdx.x * 8 + warp;
    if (t >= BB) return;

    float h[8];
#pragma unroll
    for (int j = 0; j < 8; j++) {
        const int c = lane + 32 * j;
        const float v = g_gate_acc[(size_t)t * NDFF + c];
        const float x = v * INV_WSCALE + bg1[c];
        const float inner = 0.7978845608028654f * (x + 0.044715f * x * x * x);
        h[j] = 0.5f * x * (1.0f + tanhf(inner));
    }
    float le[NE];
#pragma unroll
    for (int e = 0; e < NE; e++) {
        float s = 0.0f;
#pragma unroll
        for (int j = 0; j < 8; j++)
            s += h[j] * Wg2[(size_t)(lane + 32 * j) * NE + e];
#pragma unroll
        for (int o = 16; o > 0; o >>= 1)
            s += __shfl_xor_sync(0xffffffffu, s, o);
        le[e] = s;
    }
    if (lane == 0) {
        float logits[NE];
#pragma unroll
        for (int e = 0; e < NE; e++) logits[e] = le[e] + bg2[e];
        float mx = logits[0];
#pragma unroll
        for (int e = 1; e < NE; e++) mx = fmaxf(mx, logits[e]);
        float p[NE];
        float sum = 0.0f;
#pragma unroll
        for (int e = 0; e < NE; e++) { p[e] = expf(logits[e] - mx); sum += p[e]; }
#pragma unroll
        for (int e = 0; e < NE; e++) p[e] /= sum;
        int i1 = 0;
#pragma unroll
        for (int e = 1; e < NE; e++) if (logits[e] > logits[i1]) i1 = e;
        int i2 = (i1 == 0) ? 1 : 0;
#pragma unroll
        for (int e = 0; e < NE; e++)
            if (e != i1 && logits[e] > logits[i2]) i2 = e;
        const float denom = p[i1] + p[i2] + 1e-9f;
        int pos1 = atomicAdd(&g_counts[i1], 1);
        g_list[i1 * BB + pos1] = t;
        g_gateval[i1 * BB + pos1] = p[i1] / denom;
        g_entry[2 * t + 0] = i1 * BB + pos1;
        int pos2 = atomicAdd(&g_counts[i2], 1);
        g_list[i2 * BB + pos2] = t;
        g_gateval[i2 * BB + pos2] = p[i2] / denom;
        g_entry[2 * t + 1] = i2 * BB + pos2;
    }
}

// ---------------------------------------------------------------------------
// expert MMA (launch slot #4): balanced dynamic ragged partition.
// Tiles: per expert ceil(cnt/128), +16 general. Units = tiles x 200 chunks,
// split evenly over 148 CTAs; partials atomically accumulated.
// ---------------------------------------------------------------------------
__global__ void __launch_bounds__(256, 1)
mma_gemm_kernel() {
    __shared__ int s_tok[128];
    __shared__ int s_prefix[10];
    extern __shared__ __align__(1024) char dsm[];

    const int tid = threadIdx.x;
    const int wid = tid >> 5, lane = tid & 31;
    const int wm = wid & 1, wn = wid >> 1;

    if (tid < 10) {
        int p = 0;
        for (int e = 0; e < tid && e < 8; ++e) p += (g_counts[e] + 127) >> 7;
        if (tid == 9) p += 16;                 // general slab: 16 tiles
        s_prefix[tid] = p;
    }
    __syncthreads();
    const int U = s_prefix[9] * TCE;
    int beg = (int)(((long long)blockIdx.x * U) / NCTA);
    const int end = (int)(((long long)(blockIdx.x + 1) * U) / NCTA);

    while (beg < end) {
        const int tile = beg / TCE;
        const int cb = beg - tile * TCE;
        const int segend = min(end, (tile + 1) * TCE);
        const int nch = segend - beg;

        int slab = 0;
        while (s_prefix[slab + 1] <= tile) ++slab;
        const int t0 = (tile - s_prefix[slab]) * 128;
        const int cnt = (slab < 8) ? g_counts[slab] : BB;

        __syncthreads();   // prior segment fully done before s_tok/smem reuse
        if (tid < 128) {
            const int idx = t0 + tid;
            s_tok[tid] = (slab < 8) ? ((idx < cnt) ? g_list[slab * BB + idx] : 0) : idx;
        }
        __syncthreads();

        const __half* Wh = g_wh + (size_t)slab * FF * DM;
        const __half* Wl = g_wl + (size_t)slab * FF * DM;

        float acc[4][4][4];
#pragma unroll
        for (int a = 0; a < 4; a++)
#pragma unroll
            for (int b = 0; b < 4; b++)
#pragma unroll
                for (int c = 0; c < 4; c++) acc[a][b][c] = 0.0f;

#define EPF(CI)                                                                \
    { const int k0 = (cb + (CI)) * 64;                                         \
      const uint32_t sb = smem_u32(dsm + ((CI) % 3) * 65536);                  \
      _Pragma("unroll") for (int i = 0; i < 4; i++) {                          \
        const int q = tid + 256 * i;                                           \
        const int m = q >> 3, kb16 = q & 7;                                    \
        const uint32_t offa = (uint32_t)(m * 128 + kb16 * 16);                 \
        const uint32_t swa = offa ^ ((offa >> 3) & 0x70);                      \
        const size_t ga = (size_t)s_tok[m] * GKP + XOFF + k0 + kb16 * 8;       \
        CP16(sb + swa, g_gin_h + ga);                                          \
        CP16(sb + 16384 + swa, g_gin_l + ga);                                  \
        const int kk = q >> 4, nb16 = q & 15;                                  \
        const uint32_t offb = (uint32_t)(kk * 256 + nb16 * 16);                \
        const uint32_t swb = offb ^ ((offb >> 4) & 0x70);                      \
        const size_t gb = (size_t)(k0 + kk) * DM + nb16 * 8;                   \
        CP16(sb + 32768 + swb, Wh + gb);                                       \
        CP16(sb + 49152 + swb, Wl + gb); } }

        EPF(0);
        CP_COMMIT();
        if (nch > 1) EPF(1);
        CP_COMMIT();
        for (int c = 0; c < nch; ++c) {
            CP_WAIT1();
            __syncthreads();
            if (c + 2 < nch) EPF(c + 2);
            CP_COMMIT();
            COMPUTE_CHUNK(smem_u32(dsm + (c % 3) * 65536));
        }
#undef EPF

        float* accbuf = (slab < 8) ? g_exp_acc : g_gen_acc;
        const size_t obase = (slab < 8) ? ((size_t)slab * BB + t0) * DM
                                        : (size_t)t0 * DM;
#pragma unroll
        for (int mi = 0; mi < 4; ++mi) {
            const int r0 = wm * 64 + mi * 16 + (lane >> 2);
            const int r1 = r0 + 8;
            const bool v0 = (t0 + r0) < cnt, v1 = (t0 + r1) < cnt;
#pragma unroll
            for (int nf = 0; nf < 4; ++nf) {
                const int cc = wn * 32 + nf * 8 + (lane & 3) * 2;
                if (v0) {
                    atomicAdd(&accbuf[obase + (size_t)r0 * DM + cc],     acc[mi][nf][0]);
                    atomicAdd(&accbuf[obase + (size_t)r0 * DM + cc + 1], acc[mi][nf][1]);
                }
                if (v1) {
                    atomicAdd(&accbuf[obase + (size_t)r1 * DM + cc],     acc[mi][nf][2]);
                    atomicAdd(&accbuf[obase + (size_t)r1 * DM + cc + 1], acc[mi][nf][3]);
                }
            }
        }
        beg = segend;
    }
}

// ---------------------------------------------------------------------------
// finalize: comb = sum_{2 entries} gate*(exp_acc*inv + be); gen likewise.
// ---------------------------------------------------------------------------
__global__ void finalize_kernel(const float* __restrict__ be, const float* __restrict__ bgen,
                                float* __restrict__ out) {
    const int i = blockIdx.x * blockDim.x + threadIdx.x;
    if (i >= BB * DM) return;
    const int t = i >> 7, c = i & 127;
    float comb = 0.0f;
#pragma unroll
    for (int j = 0; j < 2; ++j) {
        const int ent = g_entry[2 * t + j];
        const int e = ent >> 11;
        const float dot = g_exp_acc[(size_t)ent * DM + c];
        comb += g_gateval[ent] * (dot * INV_WSCALE + be[e * DM + c]);
    }
    const float gen = g_gen_acc[(size_t)t * DM + c] * INV_WSCALE + bgen[c];
    out[i] = gen + __bfloat162float(__float2bfloat16(comb));
}

// ---------------------------------------------------------------------------
extern "C" void kernel_launch(void* const* d_in, const int* in_sizes, int n_in,
                              void* d_out, int out_size) {
    const float* xf   = (const float*)d_in[0];
    const float* cyc  = (const float*)d_in[1];
    const float* dkp  = (const float*)d_in[2];
    const float* Wg1  = (const float*)d_in[3];
    const float* bg1  = (const float*)d_in[4];
    const float* Wg2  = (const float*)d_in[5];
    const float* bg2  = (const float*)d_in[6];
    const float* We   = (const float*)d_in[7];
    const float* be   = (const float*)d_in[8];
    const float* Wgen = (const float*)d_in[9];
    const float* bgen = (const float*)d_in[10];
    float* out = (float*)d_out;

    cudaFuncSetAttribute(gate_mma_kernel,
                         cudaFuncAttributeMaxDynamicSharedMemorySize, 196608);
    cudaFuncSetAttribute(mma_gemm_kernel,
                         cudaFuncAttributeMaxDynamicSharedMemorySize, 196608);

    // launches: conv(1), gate(2), epilogue(3), expert(4 = ncu slot), finalize(5)
    conv_kernel<<<CBT, 256>>>(xf, cyc, dkp, Wg1, We, Wgen);
    gate_mma_kernel<<<NCTA, 256, 196608>>>();
    gate_epilogue_kernel<<<BB / 8, 256>>>(bg1, Wg2, bg2);
    mma_gemm_kernel<<<NCTA, 256, 196608>>>();
    finalize_kernel<<<(BB * DM + 255) / 256, 256>>>(be, bgen, out);
}